// round 12
// baseline (speedup 1.0000x reference)
#include <cuda_runtime.h>

// EdgeBlock warp-specialized monolithic. B=4, L=1024, N=16, D=64, W=16, V=33.
//
// R11 lesson: phase-alternating mono CTA stalls the store stream during score
// bursts (DRAM 47.8%). Fix: warp specialization. Each of 512 CTAs owns a
// (b, 8-l) tile; warps 0-5 ONLY stream value_h stores (continuous DRAM write
// stream), warps 6-7 ONLY compute window_score (su/sd dots + qc + 17 dedup'd
// window products + assembly). Score wall (~20us) hides under store wall
// (~55us); score warps exit early.
//
// Outputs (concatenated fp32 in d_out):
//   window_score (B,N,L,V)   = 2,162,688 floats
//   value_h      (B,L,V,N,D) = 138,412,032 floats (553 MB, DRAM-write bound)

#define Lc 1024
#define MASK_FILL -1e12f

__global__ void __launch_bounds__(256, 2) ws_kernel(
    const float* __restrict__ hidden,
    const int*   __restrict__ mask,
    const float* __restrict__ upon,
    const float* __restrict__ down,
    const float* __restrict__ cross,
    float*       __restrict__ out_ws,
    float4*      __restrict__ out_val)
{
    extern __shared__ float sm[];
    float* sh    = sm;                    // 24 rows x 1028 floats (98,688 B)
    float* su_s  = sm + 24672;            // [16][24] upon-dots, rows l0..l0+23
    float* sd_s  = su_s + 384;            // [16][24] down-dots, rows l0-16..l0+7
    float* qcs   = sd_s + 384;            // [2 score warps][8 l][64]
    float* prs   = qcs + 1024;            // [2 score warps][8 l][17] (pad 144)
    int*   smask = (int*)(prs + 288);     // [24]
    // total 26,792 floats = 107,168 B -> 2 CTAs/SM

    const int t   = threadIdx.x;          // 256 threads, 8 warps
    const int bid = blockIdx.x;           // 512 = b(4) x tile(128)
    const int b   = bid >> 7;
    const int l0  = (bid & 127) * 8;
    const int w   = t >> 5, lane = t & 31;

    const float4* hidden4 = (const float4*)hidden;

    // ---- stage 24 hidden rows (1024 floats each, row stride 1028) ----
#pragma unroll
    for (int r = 0; r < 24; ++r) {
        int row = (l0 + r) & (Lc - 1);
        *(float4*)&sh[r * 1028 + t * 4] = hidden4[((size_t)((b << 10) + row)) * 256 + t];
    }
    if (t < 24) smask[t] = mask[(b << 10) + ((l0 + t) & (Lc - 1))];
    __syncthreads();

    if (w < 6) {
        // ================= store warps: continuous value_h stream =============
        // 264 output rows (8 l x 33 v), 44 per warp; 8-deep STG.128 unroll.
        for (int r = w; r < 264; r += 6) {
            int ll = r / 33, v = r - ll * 33;
            int off = (v <= 16) ? 0 : (v - 16);
            const float* src = &sh[(ll + off) * 1028];
            float4* dst = &out_val[((size_t)((b << 10) + l0 + ll)) * 33 * 256
                                   + (size_t)v * 256];
#pragma unroll
            for (int k = 0; k < 8; ++k) {
                float4 val = *(const float4*)&src[(k * 32 + lane) * 4];
                __stcs(&dst[k * 32 + lane], val);
            }
        }
        return;
    }

    // ===================== score warps (w=6,7): 8 heads each ==================
    const int sw = w - 6;                 // 0 or 1
    float* qcw = &qcs[sw * 512];          // [8][64]
    float* prw = &prs[sw * 144];          // [8][17]

    // su/sd for this warp's own heads (n = sw*8 .. sw*8+7): 384 dot-64 tasks.
    for (int k = lane; k < 384; k += 32) {
        int sdf = (k >= 192);
        int kk  = sdf ? (k - 192) : k;
        int n   = sw * 8 + kk / 24, j = kk - (kk / 24) * 24;
        const float* vec = (sdf ? down : upon) + n * 64;
        float acc = 0.f;
        if (!sdf || j >= 16) {
            const float* src = &sh[(sdf ? (j - 16) : j) * 1028 + n * 64];
#pragma unroll
            for (int dq = 0; dq < 16; ++dq) {
                float4 hv = *(const float4*)&src[dq * 4];
                float4 vv = *(const float4*)&vec[dq * 4];
                acc += hv.x * vv.x + hv.y * vv.y + hv.z * vv.z + hv.w * vv.w;
            }
        } else {
            int row = (l0 - 16 + j + Lc) & (Lc - 1);
            const float4* src = (const float4*)&hidden[(((size_t)(b << 10) + row) * 16 + n) * 64];
#pragma unroll
            for (int dq = 0; dq < 16; ++dq) {
                float4 hv = __ldg(&src[dq]);
                float4 vv = *(const float4*)&vec[dq * 4];
                acc += hv.x * vv.x + hv.y * vv.y + hv.z * vv.z + hv.w * vv.w;
            }
        }
        (sdf ? sd_s : su_s)[n * 24 + j] = acc;
    }
    __syncwarp();

    for (int hh = 0; hh < 8; ++hh) {
        const int n = sw * 8 + hh;
        const float* cr = cross + n * 4096;

        // Phase A: qc[i][h] for all 8 l's; lane owns h=lane, h=lane+32.
        float a0[8] = {0,0,0,0,0,0,0,0}, a1[8] = {0,0,0,0,0,0,0,0};
#pragma unroll
        for (int dq = 0; dq < 16; ++dq) {
            float c0[4], c1[4];
#pragma unroll
            for (int j = 0; j < 4; ++j) {
                c0[j] = __ldg(&cr[(dq * 4 + j) * 64 + lane]);
                c1[j] = __ldg(&cr[(dq * 4 + j) * 64 + lane + 32]);
            }
#pragma unroll
            for (int i = 0; i < 8; ++i) {
                float4 hd = *(const float4*)&sh[i * 1028 + n * 64 + dq * 4];
                a0[i] += hd.x * c0[0] + hd.y * c0[1] + hd.z * c0[2] + hd.w * c0[3];
                a1[i] += hd.x * c1[0] + hd.y * c1[1] + hd.z * c1[2] + hd.w * c1[3];
            }
        }
#pragma unroll
        for (int i = 0; i < 8; ++i) {
            qcw[i * 64 + lane]      = a0[i];
            qcw[i * 64 + lane + 32] = a1[i];
        }
        __syncwarp();

        // Phase B: 17 distinct window products per l (lanes 0..16)
        if (lane < 17) {
            float p[8] = {0,0,0,0,0,0,0,0};
#pragma unroll
            for (int hq = 0; hq < 16; ++hq) {
#pragma unroll
                for (int i = 0; i < 8; ++i) {
                    float4 qv = *(const float4*)&qcw[i * 64 + hq * 4];
                    float4 hv = *(const float4*)&sh[(i + lane) * 1028 + n * 64 + hq * 4];
                    p[i] += qv.x * hv.x + qv.y * hv.y + qv.z * hv.z + qv.w * hv.w;
                }
            }
#pragma unroll
            for (int i = 0; i < 8; ++i) prw[i * 17 + lane] = p[i];
        }
        __syncwarp();

        // Assembly: 33 scores per l
#pragma unroll
        for (int i = 0; i < 8; ++i) {
            int l = l0 + i;
            size_t ob = ((size_t)((b * 16 + n) * Lc + l)) * 33;
#pragma unroll
            for (int vi = 0; vi < 2; ++vi) {
                int v = lane + vi * 32;
                if (v < 33) {
                    int offu = (v <= 16) ? 0 : (v - 16);
                    int offd = (v <  16) ? (v - 16) : 0;
                    float sc = prw[i * 17 + offu]
                             + su_s[n * 24 + i + offu]
                             + sd_s[n * 24 + i + offd + 16];
                    sc = (sc > 0.f) ? sc : 5.0f * sc;       // leaky_relu slope 5
                    bool m = (l + offd >= 0) && (l + offu < Lc) &&
                             (smask[i + offu] != 0);
                    __stcs(&out_ws[ob + v], m ? sc : MASK_FILL);
                }
            }
        }
        __syncwarp();   // qcw/prw reused next head
    }
}

extern "C" void kernel_launch(void* const* d_in, const int* in_sizes, int n_in,
                              void* d_out, int out_size) {
    const float* hidden = (const float*)d_in[0];
    const int*   mask   = (const int*)d_in[1];      // bool -> int32 on the wire
    const float* upon   = (const float*)d_in[2];
    const float* down   = (const float*)d_in[3];
    const float* cross  = (const float*)d_in[4];
    // d_in[5] (window_size) fixed at 16; compiled in.

    float*  out_ws  = (float*)d_out;
    float4* out_val = (float4*)(out_ws + (size_t)4 * 16 * Lc * 33); // 2,162,688 floats

    const int smem = 26792 * (int)sizeof(float);    // 107,168 B -> 2 CTAs/SM
    cudaFuncSetAttribute(ws_kernel, cudaFuncAttributeMaxDynamicSharedMemorySize, smem);

    ws_kernel<<<512, 256, smem>>>(hidden, mask, upon, down, cross,
                                  out_ws, out_val);
}

// round 13
// speedup vs baseline: 1.3415x; 1.3415x over previous
#include <cuda_runtime.h>

// EdgeBlock fused, R10 structure (1:1 CTA interleave — proven best) with a
// cheaper score path. B=4, L=1024, N=16, D=64, W=16, V=33.
//
// R12 lesson: warp-specialization starves score work of latency-hiding (2
// warps) and leaves CTA slots DRAM-idle. Reverted to R10's interleave.
// R13 change: score Phase B rebuilt as a warp-shuffle reduction. After
// Phase A, lane already holds qc[l][lane], qc[l][lane+32] in registers;
// each window product = 2 conflict-free LDS.32 + 2 FMA + 5 shfl_xor with
// ALL 32 lanes active. qcw/prw smem buffers deleted (no STS/LDS round-trip,
// no 17-lane underutilization, no stride-68 .128 conflicts). Phase A groups
// 8 l's (was 4), halving cross smem re-reads.
//
// Value path byte-identical to the proven 5764 GB/s config: 8-l tiles,
// 24 staged rows, 96 KB smem, 2 CTAs/SM, __stcs streaming stores.

#define Lc 1024
#define MASK_FILL -1e12f

__global__ void __launch_bounds__(256, 2) fused_kernel(
    const float* __restrict__ hidden,
    const int*   __restrict__ mask,
    const float* __restrict__ upon,
    const float* __restrict__ down,
    const float* __restrict__ cross,
    float*       __restrict__ out_ws,
    float4*      __restrict__ out_val)
{
    extern __shared__ float sm[];
    const int t   = threadIdx.x;
    const int bid = blockIdx.x;
    const int s   = bid >> 1;               // 0..511 within each class

    if ((bid & 1) == 0) {
        // ------------- value path: 8-l tile, 24 staged rows (96 KB) -------------
        float4* sh4 = (float4*)sm;
        const int b  = s >> 7;               // 0..3
        const int l0 = (s & 127) * 8;
        const float4* hidden4 = (const float4*)hidden;

#pragma unroll
        for (int r = 0; r < 24; ++r) {
            int row = (l0 + r) & (Lc - 1);
            sh4[r * 256 + t] = hidden4[((size_t)(b << 10) + row) * 256 + t];
        }
        __syncthreads();

        for (int ll = 0; ll < 8; ++ll) {
            size_t base = ((size_t)((b << 10) + l0 + ll)) * 33 * 256 + t;
#pragma unroll
            for (int v = 0; v < 33; ++v) {
                int off = (v <= 16) ? 0 : (v - 16);
                __stcs(&out_val[base + (size_t)v * 256], sh4[(ll + off) * 256 + t]);
            }
        }
        return;
    }

    // ------------------------- score path: s in 0..511 -------------------------
    const int tile = s & 7, n = (s >> 3) & 15, b = s >> 7;
    const int l0 = tile * 128;

    float* shC  = sm;             // [64][68]  (cross transposed: shC[h*68+d])
    float* shH  = sm + 4352;      // [160][68] (rows l0-16 .. l0+143, wrapped)
    float* su   = sm + 15232;     // [160]
    float* sd   = sm + 15392;     // [160]
    float* shup = sm + 15552;     // [64]
    float* shdn = sm + 15616;     // [64]
    int*   shm  = (int*)(sm + 15680); // [160]
    // 15840 floats = 63,360 B (value path needs 98,304 B; launch uses max)

    // cross transposed: shC[h][d] = cross[n][d][h]
    for (int i = t; i < 4096; i += 256) {
        int d2 = i >> 6, h2 = i & 63;
        shC[h2 * 68 + d2] = cross[n * 4096 + i];
    }
    if (t < 64) { shup[t] = upon[n * 64 + t]; shdn[t] = down[n * 64 + t]; }

    // shH rows l0-16 .. l0+143 (wrapped), float4 stores, stride 68
    {
        const float4* h4 = (const float4*)hidden;
        for (int i = t; i < 2560; i += 256) {         // 160 rows * 16 quads
            int rr = i >> 4, dq = i & 15;
            int row = (l0 - 16 + rr) & (Lc - 1);
            float4 v = h4[(((size_t)(b << 10) + row) * 16 + n) * 16 + dq];
            *(float4*)&shH[rr * 68 + dq * 4] = v;
        }
    }
    if (t < 160) shm[t] = mask[(b << 10) + ((l0 + t) & (Lc - 1))];
    __syncthreads();

    // per-row projection dots (float4)
    if (t < 160) {
        const float* hr = &shH[t * 68];
        float a = 0.f, c = 0.f;
#pragma unroll
        for (int dq = 0; dq < 16; ++dq) {
            float4 hv = *(const float4*)&hr[dq * 4];
            float4 up = *(const float4*)&shup[dq * 4];
            float4 dn = *(const float4*)&shdn[dq * 4];
            a += hv.x * up.x + hv.y * up.y + hv.z * up.z + hv.w * up.w;
            c += hv.x * dn.x + hv.y * dn.y + hv.z * dn.z + hv.w * dn.w;
        }
        su[t] = a; sd[t] = c;
    }
    __syncthreads();

    const int w = t >> 5, lane = t & 31;

    for (int g = 0; g < 2; ++g) {
        const int lloc0 = w * 16 + g * 8;   // 8 consecutive l's per group
        const int rb    = lloc0 + 16;       // shH row of first l

        // Phase A: qc[i][h] for 8 l's; lane owns h=lane, h=lane+32.
        // cross regs (lane-spread LDS.128) reused across all 8 l's;
        // hidden rows via broadcast LDS.128 (conflict-free).
        float a0[8] = {0,0,0,0,0,0,0,0}, a1[8] = {0,0,0,0,0,0,0,0};
#pragma unroll
        for (int dq = 0; dq < 16; ++dq) {
            float4 c0 = *(const float4*)&shC[lane * 68 + dq * 4];
            float4 c1 = *(const float4*)&shC[(lane + 32) * 68 + dq * 4];
#pragma unroll
            for (int i = 0; i < 8; ++i) {
                float4 hd = *(const float4*)&shH[(rb + i) * 68 + dq * 4];
                a0[i] += hd.x * c0.x + hd.y * c0.y + hd.z * c0.z + hd.w * c0.w;
                a1[i] += hd.x * c1.x + hd.y * c1.y + hd.z * c1.z + hd.w * c1.w;
            }
        }

        // Phase B: 17 window products per l via shuffle reduction.
        // p(i,o) = sum_h qc[i][h] * shH[rb+i+o][h]; lane contributes h=lane
        // and h=lane+32, then 5-step bfly sum; lane o keeps p(i,o).
        float pk[8];
#pragma unroll
        for (int i = 0; i < 8; ++i) {
            pk[i] = 0.f;
            for (int o = 0; o < 17; ++o) {
                const float* hr = &shH[(rb + i + o) * 68];
                float p = a0[i] * hr[lane] + a1[i] * hr[lane + 32];
#pragma unroll
                for (int d2 = 16; d2 > 0; d2 >>= 1)
                    p += __shfl_xor_sync(0xffffffffu, p, d2);
                if (lane == o) pk[i] = p;
            }
        }

        // Assembly: 33 scores per l. prod for lane v comes from lane offu(v).
#pragma unroll
        for (int i = 0; i < 8; ++i) {
            const int lloc = lloc0 + i, l = l0 + lloc, rbl = rb + i;
            size_t ob = ((size_t)((b * 16 + n) * Lc + l)) * 33;

            // v = lane (0..31)
            {
                int v = lane;
                int offu = (v <= 16) ? 0 : (v - 16);
                int offd = (v <  16) ? (v - 16) : 0;
                float prod = __shfl_sync(0xffffffffu, pk[i], offu);
                float sc = prod + su[rbl + offu] + sd[rbl + offd];
                sc = (sc > 0.f) ? sc : 5.0f * sc;           // leaky_relu slope 5
                bool m = (l + offd >= 0) && (l + offu < Lc) &&
                         (shm[lloc + offu] != 0);
                __stcs(&out_ws[ob + v], m ? sc : MASK_FILL);
            }
            // v = 32 (lane 0 writes; shuffle executed by all lanes)
            {
                float prod32 = __shfl_sync(0xffffffffu, pk[i], 16);
                if (lane == 0) {
                    float sc = prod32 + su[rbl + 16] + sd[rbl];
                    sc = (sc > 0.f) ? sc : 5.0f * sc;
                    bool m = (l + 16 < Lc) && (shm[lloc + 16] != 0);
                    __stcs(&out_ws[ob + 32], m ? sc : MASK_FILL);
                }
            }
        }
    }
}

extern "C" void kernel_launch(void* const* d_in, const int* in_sizes, int n_in,
                              void* d_out, int out_size) {
    const float* hidden = (const float*)d_in[0];
    const int*   mask   = (const int*)d_in[1];      // bool -> int32 on the wire
    const float* upon   = (const float*)d_in[2];
    const float* down   = (const float*)d_in[3];
    const float* cross  = (const float*)d_in[4];
    // d_in[5] (window_size) fixed at 16; compiled in.

    float*  out_ws  = (float*)d_out;
    float4* out_val = (float4*)(out_ws + (size_t)4 * 16 * Lc * 33); // 2,162,688 floats

    const int smem = 24 * 256 * (int)sizeof(float4);   // 98,304 B (value path max)
    cudaFuncSetAttribute(fused_kernel, cudaFuncAttributeMaxDynamicSharedMemorySize, smem);

    // 1024 blocks, 1:1 interleave: even bid = value, odd bid = score.
    fused_kernel<<<1024, 256, smem>>>(hidden, mask, upon, down, cross,
                                      out_ws, out_val);
}